// round 1
// baseline (speedup 1.0000x reference)
#include <cuda_runtime.h>

// Shift_7292854469289
// out[b,c,h,w] = x[b,c, clamp(h + trunc(ypos[h]*stride), 0, H-1),
//                      clamp(w + trunc(xpos[w]*stride), 0, W-1)]
// B=16, C=64, H=W=256, fp32. Pure DRAM-bound gather: 512 MiB traffic.

#define H_ 256
#define W_ 256

// Fast path: H=W=256, each thread produces one float4 (4 consecutive w).
__global__ void __launch_bounds__(256) shift_kernel_256(
    const float* __restrict__ x,
    const float* __restrict__ xpos,
    const float* __restrict__ ypos,
    const int*   __restrict__ stride_p,
    float4*      __restrict__ out4)
{
    const int stride = *stride_p;  // uniform, L1/const-cached after first access

    unsigned int tid = blockIdx.x * blockDim.x + threadIdx.x;  // over total/4
    // layout: tid = ((bc*H + h) * (W/4) + w4)
    int w4   = tid & 63;          // W/4 = 64
    unsigned int rest = tid >> 6;
    int h    = rest & 255;        // H = 256
    unsigned int bc = rest >> 8;  // b*C + c, 0..1023

    // source row (truncate toward zero == C cast)
    int sy   = (int)(ypos[h] * (float)stride);
    int srcH = min(max(h + sy, 0), H_ - 1);

    const float* __restrict__ row = x + ((size_t)(bc << 8) + (size_t)srcH) * (size_t)W_;

    int w0 = w4 << 2;
    float4 v;
    {
        int w = w0 + 0;
        int sw = min(max(w + (int)(xpos[w] * (float)stride), 0), W_ - 1);
        v.x = __ldg(row + sw);
    }
    {
        int w = w0 + 1;
        int sw = min(max(w + (int)(xpos[w] * (float)stride), 0), W_ - 1);
        v.y = __ldg(row + sw);
    }
    {
        int w = w0 + 2;
        int sw = min(max(w + (int)(xpos[w] * (float)stride), 0), W_ - 1);
        v.z = __ldg(row + sw);
    }
    {
        int w = w0 + 3;
        int sw = min(max(w + (int)(xpos[w] * (float)stride), 0), W_ - 1);
        v.w = __ldg(row + sw);
    }

    out4[tid] = v;
}

// Generic fallback (any H, W): one thread per element.
__global__ void shift_kernel_generic(
    const float* __restrict__ x,
    const float* __restrict__ xpos,
    const float* __restrict__ ypos,
    const int*   __restrict__ stride_p,
    float*       __restrict__ out,
    int H, int W, long long total)
{
    const int stride = *stride_p;
    long long i = (long long)blockIdx.x * blockDim.x + threadIdx.x;
    if (i >= total) return;
    int w = (int)(i % W);
    long long r = i / W;
    int h = (int)(r % H);
    long long bc = r / H;

    int srcH = min(max(h + (int)(ypos[h] * (float)stride), 0), H - 1);
    int srcW = min(max(w + (int)(xpos[w] * (float)stride), 0), W - 1);
    out[i] = x[(bc * H + srcH) * (long long)W + srcW];
}

extern "C" void kernel_launch(void* const* d_in, const int* in_sizes, int n_in,
                              void* d_out, int out_size)
{
    const float* x      = (const float*)d_in[0];
    const float* xpos   = (const float*)d_in[1];
    const float* ypos   = (const float*)d_in[2];
    const int*   stride = (const int*)d_in[3];
    float* out = (float*)d_out;

    int W = in_sizes[1];   // xpos has W elements
    int H = in_sizes[2];   // ypos has H elements

    if (H == 256 && W == 256 && (out_size & 3) == 0) {
        int n4 = out_size >> 2;             // 16,777,216
        int threads = 256;
        int blocks = (n4 + threads - 1) / threads;  // 65536
        shift_kernel_256<<<blocks, threads>>>(x, xpos, ypos, stride, (float4*)out);
    } else {
        long long total = out_size;
        int threads = 256;
        long long blocks = (total + threads - 1) / threads;
        shift_kernel_generic<<<(unsigned int)blocks, threads>>>(
            x, xpos, ypos, stride, out, H, W, total);
    }
}

// round 2
// speedup vs baseline: 1.1797x; 1.1797x over previous
#include <cuda_runtime.h>

// Shift_7292854469289  — out[b,c,h,w] = x[b,c, srcH[h], srcW[w]]
// srcH[h] = clamp(h + trunc(ypos[h]*stride), 0, H-1)
// srcW[w] = clamp(w + trunc(xpos[w]*stride), 0, W-1)
// B=16, C=64, H=W=256, fp32. DRAM-bound permutation-gather: ~537 MB traffic.

#define H_ 256
#define W_ 256
#define W4_ 64                 // W/4
#define IMG4 (H_ * W4_)        // float4 elements per (b,c) plane
#define BC_PER 4               // bc planes per thread

// --- precomputed index tables (device globals: no allocation allowed) ---
__device__ int g_srcH[H_];
__device__ int g_srcW[W_];
__device__ int g_vq[W4_];      // float4-index of quad if aligned+contiguous, else -1

__global__ void precompute_kernel(const float* __restrict__ xpos,
                                  const float* __restrict__ ypos,
                                  const int*   __restrict__ stride_p)
{
    const int stride = *stride_p;
    int t = threadIdx.x;                      // 256 threads
    // trunc toward zero == C float->int cast (matches Python int())
    int sy = (int)(ypos[t] * (float)stride);
    g_srcH[t] = min(max(t + sy, 0), H_ - 1);
    int sw = min(max(t + (int)(xpos[t] * (float)stride), 0), W_ - 1);
    g_srcW[t] = sw;
    __syncthreads();
    if (t < W4_) {
        int s0 = g_srcW[4 * t];
        bool ok = ((s0 & 3) == 0)
               && (g_srcW[4 * t + 1] == s0 + 1)
               && (g_srcW[4 * t + 2] == s0 + 2)
               && (g_srcW[4 * t + 3] == s0 + 3);
        g_vq[t] = ok ? (s0 >> 2) : -1;
    }
}

// Main kernel: each thread produces one float4 for BC_PER consecutive bc planes.
// Within a warp: h and bcg uniform, w4 consecutive -> all loads/stores are
// unit-stride float4 across lanes = 128B/wavefront optimal.
__global__ void __launch_bounds__(256) shift_main_kernel(
    const float4* __restrict__ x4,
    float4*       __restrict__ out4)
{
    __shared__ int s_srcH[H_];
    __shared__ int s_srcW[W_];
    __shared__ int s_vq[W4_];

    int t = threadIdx.x;
    s_srcH[t] = g_srcH[t];
    s_srcW[t] = g_srcW[t];
    if (t < W4_) s_vq[t] = g_vq[t];
    __syncthreads();

    unsigned int tid = blockIdx.x * 256u + t;   // over 256(bcg) x 256(h) x 64(w4)
    int w4  = tid & 63;
    int h   = (tid >> 6) & 255;
    unsigned int bcg = tid >> 14;               // 0..255
    unsigned int bc0 = bcg * BC_PER;

    int srcH = s_srcH[h];
    int vq   = s_vq[w4];

    size_t in_row  = (size_t)srcH * W4_;
    size_t out_idx = (size_t)bc0 * IMG4 + (size_t)h * W4_ + w4;

    if (vq >= 0) {
        size_t in_idx = (size_t)bc0 * IMG4 + in_row + vq;
        // 4 independent LDG.128 (MLP=4), then 4 ST.128
        float4 v0 = __ldg(x4 + in_idx);
        float4 v1 = __ldg(x4 + in_idx + IMG4);
        float4 v2 = __ldg(x4 + in_idx + 2 * IMG4);
        float4 v3 = __ldg(x4 + in_idx + 3 * IMG4);
        out4[out_idx]            = v0;
        out4[out_idx + IMG4]     = v1;
        out4[out_idx + 2 * IMG4] = v2;
        out4[out_idx + 3 * IMG4] = v3;
    } else {
        // general path: per-component gather
        int sw0 = s_srcW[4 * w4 + 0];
        int sw1 = s_srcW[4 * w4 + 1];
        int sw2 = s_srcW[4 * w4 + 2];
        int sw3 = s_srcW[4 * w4 + 3];
        const float* xf = (const float*)x4;
        #pragma unroll
        for (int i = 0; i < BC_PER; i++) {
            const float* row = xf + ((size_t)(bc0 + i) * IMG4 + in_row) * 4;
            float4 v;
            v.x = __ldg(row + sw0);
            v.y = __ldg(row + sw1);
            v.z = __ldg(row + sw2);
            v.w = __ldg(row + sw3);
            out4[out_idx + (size_t)i * IMG4] = v;
        }
    }
}

// Generic fallback (any H, W): one thread per element.
__global__ void shift_kernel_generic(
    const float* __restrict__ x,
    const float* __restrict__ xpos,
    const float* __restrict__ ypos,
    const int*   __restrict__ stride_p,
    float*       __restrict__ out,
    int H, int W, long long total)
{
    const int stride = *stride_p;
    long long i = (long long)blockIdx.x * blockDim.x + threadIdx.x;
    if (i >= total) return;
    int w = (int)(i % W);
    long long r = i / W;
    int h = (int)(r % H);
    long long bc = r / H;

    int srcH = min(max(h + (int)(ypos[h] * (float)stride), 0), H - 1);
    int srcW = min(max(w + (int)(xpos[w] * (float)stride), 0), W - 1);
    out[i] = x[(bc * H + srcH) * (long long)W + srcW];
}

extern "C" void kernel_launch(void* const* d_in, const int* in_sizes, int n_in,
                              void* d_out, int out_size)
{
    const float* x      = (const float*)d_in[0];
    const float* xpos   = (const float*)d_in[1];
    const float* ypos   = (const float*)d_in[2];
    const int*   stride = (const int*)d_in[3];
    float* out = (float*)d_out;

    int W = in_sizes[1];   // xpos has W elements
    int H = in_sizes[2];   // ypos has H elements

    long long total = out_size;
    long long bc_total = total / ((long long)H * W);   // B*C

    if (H == 256 && W == 256 && bc_total == 1024) {
        precompute_kernel<<<1, 256>>>(xpos, ypos, stride);
        // threads = (1024/4 bc groups) * 256 h * 64 w4 = 4,194,304
        shift_main_kernel<<<16384, 256>>>((const float4*)x, (float4*)out);
    } else {
        int threads = 256;
        long long blocks = (total + threads - 1) / threads;
        shift_kernel_generic<<<(unsigned int)blocks, threads>>>(
            x, xpos, ypos, stride, out, H, W, total);
    }
}

// round 3
// speedup vs baseline: 1.1996x; 1.0169x over previous
#include <cuda_runtime.h>

// Shift_7292854469289  — out[b,c,h,w] = x[b,c, srcH[h], srcW[w]]
// srcH[h] = clamp(h + trunc(ypos[h]*stride), 0, H-1)
// srcW[w] = clamp(w + trunc(xpos[w]*stride), 0, W-1)
// B=16, C=64, H=W=256, fp32. DRAM-bound permutation-gather.
// Single fused kernel: per-block smem index tables + 8-deep MLP float4 pipeline.

#define H_ 256
#define W_ 256
#define W4_ 64                 // W/4
#define IMG4 (H_ * W4_)        // float4 elements per (b,c) plane
#define BC_PER 8               // bc planes per thread

// Main kernel: each thread produces one float4 (h, w4) for BC_PER consecutive
// bc planes. Within a warp: h, bcg uniform; w4 consecutive -> every load and
// store is unit-stride float4 across lanes = 128B/wavefront optimal.
__global__ void __launch_bounds__(256) shift_fused_kernel(
    const float4* __restrict__ x4,
    const float*  __restrict__ xpos,
    const float*  __restrict__ ypos,
    const int*    __restrict__ stride_p,
    float4*       __restrict__ out4)
{
    __shared__ int s_srcH[H_];
    __shared__ int s_srcW[W_];
    __shared__ int s_vq[W4_];

    const int t = threadIdx.x;
    {
        const int stride = *stride_p;
        // trunc toward zero == C float->int cast (matches Python int())
        int sy = (int)(ypos[t] * (float)stride);
        s_srcH[t] = min(max(t + sy, 0), H_ - 1);
        s_srcW[t] = min(max(t + (int)(xpos[t] * (float)stride), 0), W_ - 1);
    }
    __syncthreads();
    if (t < W4_) {
        int s0 = s_srcW[4 * t];
        bool ok = ((s0 & 3) == 0)
               && (s_srcW[4 * t + 1] == s0 + 1)
               && (s_srcW[4 * t + 2] == s0 + 2)
               && (s_srcW[4 * t + 3] == s0 + 3);
        s_vq[t] = ok ? (s0 >> 2) : -1;
    }
    __syncthreads();

    unsigned int tid = blockIdx.x * 256u + t;   // over 128(bcg) x 256(h) x 64(w4)
    int w4  = tid & 63;
    int h   = (tid >> 6) & 255;
    unsigned int bcg = tid >> 14;               // 0..127
    unsigned int bc0 = bcg * BC_PER;

    int srcH = s_srcH[h];
    int vq   = s_vq[w4];

    size_t in_row  = (size_t)srcH * W4_;
    size_t out_idx = (size_t)bc0 * IMG4 + (size_t)h * W4_ + w4;

    if (vq >= 0) {
        size_t in_idx = (size_t)bc0 * IMG4 + in_row + vq;
        // 8 independent LDG.128 in flight, then 8 streaming ST.128
        float4 v[BC_PER];
        #pragma unroll
        for (int i = 0; i < BC_PER; i++)
            v[i] = __ldg(x4 + in_idx + (size_t)i * IMG4);
        #pragma unroll
        for (int i = 0; i < BC_PER; i++)
            __stcs(out4 + out_idx + (size_t)i * IMG4, v[i]);
    } else {
        // general path: per-component gather
        int sw0 = s_srcW[4 * w4 + 0];
        int sw1 = s_srcW[4 * w4 + 1];
        int sw2 = s_srcW[4 * w4 + 2];
        int sw3 = s_srcW[4 * w4 + 3];
        const float* xf = (const float*)x4;
        #pragma unroll
        for (int i = 0; i < BC_PER; i++) {
            const float* row = xf + ((size_t)(bc0 + i) * IMG4 + in_row) * 4;
            float4 v;
            v.x = __ldg(row + sw0);
            v.y = __ldg(row + sw1);
            v.z = __ldg(row + sw2);
            v.w = __ldg(row + sw3);
            __stcs(out4 + out_idx + (size_t)i * IMG4, v);
        }
    }
}

// Generic fallback (any H, W): one thread per element.
__global__ void shift_kernel_generic(
    const float* __restrict__ x,
    const float* __restrict__ xpos,
    const float* __restrict__ ypos,
    const int*   __restrict__ stride_p,
    float*       __restrict__ out,
    int H, int W, long long total)
{
    const int stride = *stride_p;
    long long i = (long long)blockIdx.x * blockDim.x + threadIdx.x;
    if (i >= total) return;
    int w = (int)(i % W);
    long long r = i / W;
    int h = (int)(r % H);
    long long bc = r / H;

    int srcH = min(max(h + (int)(ypos[h] * (float)stride), 0), H - 1);
    int srcW = min(max(w + (int)(xpos[w] * (float)stride), 0), W - 1);
    out[i] = x[(bc * H + srcH) * (long long)W + srcW];
}

extern "C" void kernel_launch(void* const* d_in, const int* in_sizes, int n_in,
                              void* d_out, int out_size)
{
    const float* x      = (const float*)d_in[0];
    const float* xpos   = (const float*)d_in[1];
    const float* ypos   = (const float*)d_in[2];
    const int*   stride = (const int*)d_in[3];
    float* out = (float*)d_out;

    int W = in_sizes[1];   // xpos has W elements
    int H = in_sizes[2];   // ypos has H elements

    long long total = out_size;
    long long bc_total = total / ((long long)H * W);   // B*C

    if (H == 256 && W == 256 && bc_total == 1024) {
        // threads = (1024/8 bc groups) * 256 h * 64 w4 = 2,097,152 -> 8192 blocks
        shift_fused_kernel<<<8192, 256>>>((const float4*)x, xpos, ypos, stride,
                                          (float4*)out);
    } else {
        int threads = 256;
        long long blocks = (total + threads - 1) / threads;
        shift_kernel_generic<<<(unsigned int)blocks, threads>>>(
            x, xpos, ypos, stride, out, H, W, total);
    }
}

// round 5
// speedup vs baseline: 1.2060x; 1.0053x over previous
#include <cuda_runtime.h>
#include <cstdint>

// Shift_7292854469289  — out[b,c,h,w] = x[b,c, srcH[h], srcW[w]]
// srcH[h] = clamp(h + trunc(ypos[h]*stride), 0, H-1)
// srcW[w] = clamp(w + trunc(xpos[w]*stride), 0, W-1)
// B=16, C=64, H=W=256, fp32. DRAM-bound permutation-gather (~394MB real traffic).
// R5: zero smem, zero barriers — per-thread register index math, 8-plane MLP.

#define H_ 256
#define W_ 256
#define W4_ 64                 // W/4
#define IMG4 (H_ * W4_)        // float4 elements per (b,c) plane
#define BC_PER 8               // bc planes per thread

__global__ void __launch_bounds__(256) shift_reg_kernel(
    const float4* __restrict__ x4,
    const float4* __restrict__ xpos4,
    const float*  __restrict__ ypos,
    const int*    __restrict__ stride_p,
    float4*       __restrict__ out4)
{
    unsigned int tid = blockIdx.x * 256u + threadIdx.x; // 128(bcg) x 256(h) x 64(w4)
    int w4  = tid & 63;
    int h   = (tid >> 6) & 255;
    unsigned int bcg = tid >> 14;               // 0..127
    unsigned int bc0 = bcg * BC_PER;

    const int stride = *stride_p;               // L2/L1-resident scalar

    // ---- index math entirely in registers (no smem, no sync) ----
    // trunc toward zero == C float->int cast (matches Python int())
    int srcH = min(max(h + (int)(ypos[h] * (float)stride), 0), H_ - 1);

    float4 xp = __ldg(xpos4 + w4);              // xpos[4w4 .. 4w4+3]
    int w0  = w4 << 2;
    int sw0 = min(max(w0     + (int)(xp.x * (float)stride), 0), W_ - 1);
    int sw1 = min(max(w0 + 1 + (int)(xp.y * (float)stride), 0), W_ - 1);
    int sw2 = min(max(w0 + 2 + (int)(xp.z * (float)stride), 0), W_ - 1);
    int sw3 = min(max(w0 + 3 + (int)(xp.w * (float)stride), 0), W_ - 1);

    bool vec = ((sw0 & 3) == 0) & (sw1 == sw0 + 1) & (sw2 == sw0 + 2)
                                & (sw3 == sw0 + 3);

    size_t in_row  = (size_t)srcH * W4_;
    size_t out_idx = (size_t)bc0 * IMG4 + (size_t)h * W4_ + w4;

    if (vec) {
        size_t in_idx = (size_t)bc0 * IMG4 + in_row + (sw0 >> 2);
        float4 v[BC_PER];
        #pragma unroll
        for (int i = 0; i < BC_PER; i++)
            v[i] = __ldg(x4 + in_idx + (size_t)i * IMG4);
        #pragma unroll
        for (int i = 0; i < BC_PER; i++)
            __stcs(out4 + out_idx + (size_t)i * IMG4, v[i]);
    } else {
        const float* xf = (const float*)x4;
        #pragma unroll
        for (int i = 0; i < BC_PER; i++) {
            const float* row = xf + ((size_t)(bc0 + i) * IMG4 + in_row) * 4;
            float4 v;
            v.x = __ldg(row + sw0);
            v.y = __ldg(row + sw1);
            v.z = __ldg(row + sw2);
            v.w = __ldg(row + sw3);
            __stcs(out4 + out_idx + (size_t)i * IMG4, v);
        }
    }
}

// Generic fallback (any H, W): one thread per element.
__global__ void shift_kernel_generic(
    const float* __restrict__ x,
    const float* __restrict__ xpos,
    const float* __restrict__ ypos,
    const int*   __restrict__ stride_p,
    float*       __restrict__ out,
    int H, int W, long long total)
{
    const int stride = *stride_p;
    long long i = (long long)blockIdx.x * blockDim.x + threadIdx.x;
    if (i >= total) return;
    int w = (int)(i % W);
    long long r = i / W;
    int h = (int)(r % H);
    long long bc = r / H;

    int srcH = min(max(h + (int)(ypos[h] * (float)stride), 0), H - 1);
    int srcW = min(max(w + (int)(xpos[w] * (float)stride), 0), W - 1);
    out[i] = x[(bc * H + srcH) * (long long)W + srcW];
}

extern "C" void kernel_launch(void* const* d_in, const int* in_sizes, int n_in,
                              void* d_out, int out_size)
{
    const float* x      = (const float*)d_in[0];
    const float* xpos   = (const float*)d_in[1];
    const float* ypos   = (const float*)d_in[2];
    const int*   stride = (const int*)d_in[3];
    float* out = (float*)d_out;

    int W = in_sizes[1];   // xpos has W elements
    int H = in_sizes[2];   // ypos has H elements

    long long total = out_size;
    long long bc_total = total / ((long long)H * W);   // B*C

    if (H == 256 && W == 256 && bc_total == 1024 &&
        ((((uintptr_t)xpos) & 15) == 0)) {
        // threads = (1024/8 bc groups) * 256 h * 64 w4 = 2,097,152 -> 8192 blocks
        shift_reg_kernel<<<8192, 256>>>((const float4*)x, (const float4*)xpos,
                                        ypos, stride, (float4*)out);
    } else {
        int threads = 256;
        long long blocks = (total + threads - 1) / threads;
        shift_kernel_generic<<<(unsigned int)blocks, threads>>>(
            x, xpos, ypos, stride, out, H, W, total);
    }
}

// round 6
// speedup vs baseline: 1.2346x; 1.0237x over previous
#include <cuda_runtime.h>
#include <cstdint>

// Shift_7292854469289  — out[b,c,h,w] = x[b,c, srcH[h], srcW[w]]
// srcH[h] = clamp(h + trunc(ypos[h]*stride), 0, H-1)
// srcW[w] = clamp(w + trunc(xpos[w]*stride), 0, W-1)
// B=16, C=64, H=W=256, fp32. DRAM-bound permutation-gather (~394MB real traffic).
// R6: register index math (no smem/barriers) + BC_PER=4 + plain stores
//     (the two empirically-best configs combined).

#define H_ 256
#define W_ 256
#define W4_ 64                 // W/4
#define IMG4 (H_ * W4_)        // float4 elements per (b,c) plane
#define BC_PER 4               // bc planes per thread

__global__ void __launch_bounds__(256) shift_reg4_kernel(
    const float4* __restrict__ x4,
    const float4* __restrict__ xpos4,
    const float*  __restrict__ ypos,
    const int*    __restrict__ stride_p,
    float4*       __restrict__ out4)
{
    unsigned int tid = blockIdx.x * 256u + threadIdx.x; // 256(bcg) x 256(h) x 64(w4)
    int w4  = tid & 63;
    int h   = (tid >> 6) & 255;
    unsigned int bcg = tid >> 14;               // 0..255
    unsigned int bc0 = bcg * BC_PER;

    const int stride = *stride_p;               // L2/L1-resident scalar

    // ---- index math entirely in registers ----
    // trunc toward zero == C float->int cast (matches Python int())
    int srcH = min(max(h + (int)(ypos[h] * (float)stride), 0), H_ - 1);

    float4 xp = __ldg(xpos4 + w4);              // xpos[4w4 .. 4w4+3]
    int w0  = w4 << 2;
    int sw0 = min(max(w0     + (int)(xp.x * (float)stride), 0), W_ - 1);
    int sw1 = min(max(w0 + 1 + (int)(xp.y * (float)stride), 0), W_ - 1);
    int sw2 = min(max(w0 + 2 + (int)(xp.z * (float)stride), 0), W_ - 1);
    int sw3 = min(max(w0 + 3 + (int)(xp.w * (float)stride), 0), W_ - 1);

    bool vec = ((sw0 & 3) == 0) & (sw1 == sw0 + 1) & (sw2 == sw0 + 2)
                                & (sw3 == sw0 + 3);

    size_t in_row  = (size_t)srcH * W4_;
    size_t out_idx = (size_t)bc0 * IMG4 + (size_t)h * W4_ + w4;

    if (vec) {
        size_t in_idx = (size_t)bc0 * IMG4 + in_row + (sw0 >> 2);
        float4 v0 = __ldg(x4 + in_idx);
        float4 v1 = __ldg(x4 + in_idx + IMG4);
        float4 v2 = __ldg(x4 + in_idx + 2 * IMG4);
        float4 v3 = __ldg(x4 + in_idx + 3 * IMG4);
        out4[out_idx]            = v0;
        out4[out_idx + IMG4]     = v1;
        out4[out_idx + 2 * IMG4] = v2;
        out4[out_idx + 3 * IMG4] = v3;
    } else {
        const float* xf = (const float*)x4;
        #pragma unroll
        for (int i = 0; i < BC_PER; i++) {
            const float* row = xf + ((size_t)(bc0 + i) * IMG4 + in_row) * 4;
            float4 v;
            v.x = __ldg(row + sw0);
            v.y = __ldg(row + sw1);
            v.z = __ldg(row + sw2);
            v.w = __ldg(row + sw3);
            out4[out_idx + (size_t)i * IMG4] = v;
        }
    }
}

// Generic fallback (any H, W): one thread per element.
__global__ void shift_kernel_generic(
    const float* __restrict__ x,
    const float* __restrict__ xpos,
    const float* __restrict__ ypos,
    const int*   __restrict__ stride_p,
    float*       __restrict__ out,
    int H, int W, long long total)
{
    const int stride = *stride_p;
    long long i = (long long)blockIdx.x * blockDim.x + threadIdx.x;
    if (i >= total) return;
    int w = (int)(i % W);
    long long r = i / W;
    int h = (int)(r % H);
    long long bc = r / H;

    int srcH = min(max(h + (int)(ypos[h] * (float)stride), 0), H - 1);
    int srcW = min(max(w + (int)(xpos[w] * (float)stride), 0), W - 1);
    out[i] = x[(bc * H + srcH) * (long long)W + srcW];
}

extern "C" void kernel_launch(void* const* d_in, const int* in_sizes, int n_in,
                              void* d_out, int out_size)
{
    const float* x      = (const float*)d_in[0];
    const float* xpos   = (const float*)d_in[1];
    const float* ypos   = (const float*)d_in[2];
    const int*   stride = (const int*)d_in[3];
    float* out = (float*)d_out;

    int W = in_sizes[1];   // xpos has W elements
    int H = in_sizes[2];   // ypos has H elements

    long long total = out_size;
    long long bc_total = total / ((long long)H * W);   // B*C

    if (H == 256 && W == 256 && bc_total == 1024 &&
        ((((uintptr_t)xpos) & 15) == 0)) {
        // threads = (1024/4 bc groups) * 256 h * 64 w4 = 4,194,304 -> 16384 blocks
        shift_reg4_kernel<<<16384, 256>>>((const float4*)x, (const float4*)xpos,
                                          ypos, stride, (float4*)out);
    } else {
        int threads = 256;
        long long blocks = (total + threads - 1) / threads;
        shift_kernel_generic<<<(unsigned int)blocks, threads>>>(
            x, xpos, ypos, stride, out, H, W, total);
    }
}